// round 5
// baseline (speedup 1.0000x reference)
#include <cuda_runtime.h>
#include <cstdint>
#include <math.h>

#define FDIM 256
#define NB 8
#define NPATH 20
#define BDIM 8192
#define NSLAB (BDIM / 16)          // 512 b-slabs of 16
#define KC 16                      // k per pipeline chunk
#define NCHUNK (FDIM / KC)         // 16
#define GBN 64                     // n per CTA

// smem budget (bytes)
#define A_STAGE_B 8192
#define B_STAGE_B 32768
#define STAGE_B (A_STAGE_B + B_STAGE_B)     // 40960
#define PIPE_B (2 * STAGE_B)                // 81920
// epilogue regions (after pipeline is dead): eS 64KB @0, wc @65536, sig, bias
#define WC_OFF_F 16384
#define SIG_OFF_F 20544
#define BIAS_OFF_F 20800
#define SMEM_TOTAL 83456

// ---------------- scratch (device globals) ----------------
// A, fragment-packed, fused-plane: [slab 512][kc 16][plane 8][k8 2][lane 32][j 4]
__device__ float g_xt[(size_t)NSLAB * NCHUNK * 2048];      // 64MB
// B, fragment-packed: [kc 16][g 4][s 2][n8 32][k8 2][lane 32][h 2]
__device__ float g_wt[(size_t)NCHUNK * 8 * 32 * 128];      // 2MB
__device__ float g_Wc[FDIM * 64];
__device__ float g_sig[FDIM * 4];

__constant__ int c_masks[8] = {0, 1, 2, 4, 3, 5, 6, 7};
__constant__ int c_plut[64] = {
     0, -1, -1, -1,   -1,  1, -1, -1,   -1, -1,  2, -1,   -1, -1, -1,  3,
    -1,  4, -1, -1,    5, -1,  6, -1,   -1,  7, -1,  8,   -1, -1,  9, -1,
    -1, -1, 10, -1,   -1, 11, -1, 12,   13, -1, 14, -1,   -1, 15, -1, -1,
    -1, -1, -1, 16,   -1, -1, 17, -1,   -1, 18, -1, -1,   19, -1, -1, -1
};

// ---------------- helpers ----------------
__device__ __forceinline__ uint32_t to_tf32(float f) {
    uint32_t r;
    asm("cvt.rna.tf32.f32 %0, %1;" : "=r"(r) : "f"(f));
    return r;
}
__device__ __forceinline__ uint32_t smem_u32(const void* p) {
    uint32_t r;
    asm("{ .reg .u64 t; cvta.to.shared.u64 t, %1; cvt.u32.u64 %0, t; }" : "=r"(r) : "l"(p));
    return r;
}
__device__ __forceinline__ void cp16(uint32_t sdst, const void* gsrc) {
    asm volatile("cp.async.cg.shared.global [%0], [%1], 16;" :: "r"(sdst), "l"(gsrc));
}
__device__ __forceinline__ void cp_commit() { asm volatile("cp.async.commit_group;"); }
template <int N> __device__ __forceinline__ void cp_wait() {
    asm volatile("cp.async.wait_group %0;" :: "n"(N));
}
__device__ __forceinline__ void mma_tf32(float* c, const uint32_t* a, const uint32_t* b) {
    asm volatile(
        "mma.sync.aligned.m16n8k8.row.col.f32.tf32.tf32.f32 "
        "{%0,%1,%2,%3}, {%4,%5,%6,%7}, {%8,%9}, {%0,%1,%2,%3};"
        : "+f"(c[0]), "+f"(c[1]), "+f"(c[2]), "+f"(c[3])
        : "r"(a[0]), "r"(a[1]), "r"(a[2]), "r"(a[3]), "r"(b[0]), "r"(b[1]));
}

// ---------------------------------------------------------------------------
// prep: Wc[n][i][k] = sign(m_i,m_k) * w_gp[n, path], sig = sigmoid(a_norm)
// ---------------------------------------------------------------------------
__global__ void sgp_prep(const float* __restrict__ w_gp,
                         const float* __restrict__ a_norm) {
    int n = blockIdx.x;
    int t = threadIdx.x;
    int i = t >> 3, k = t & 7;
    int mi = c_masks[i], mk = c_masks[k];
    int gi = __popc(mi), gj = __popc(mi ^ mk), gk = __popc(mk);
    int p = c_plut[gi * 16 + gj * 4 + gk];
    int s = 0, aa = mi >> 1;
    while (aa) { s += __popc(aa & mk); aa >>= 1; }
    float sgn = (s & 1) ? -1.0f : 1.0f;
    g_Wc[n * 64 + t] = sgn * w_gp[n * NPATH + p];
    if (t < 4) g_sig[n * 4 + t] = 1.0f / (1.0f + expf(-a_norm[n * 4 + t]));
}

// ---------------------------------------------------------------------------
// B pack: one thread = one (lane,h-pair) fragment slot (2 floats)
// g_wt[((((kc*4+g)*2+s)*32+n8)*2+k8)*64 + lane*2 + h] = tf32(w_s[n][k(h)][g])
// ---------------------------------------------------------------------------
__global__ void __launch_bounds__(256) sgp_wprep(const float* __restrict__ wL,
                                                 const float* __restrict__ wR) {
    int pid = blockIdx.x * 256 + threadIdx.x;   // 0 .. 262143
    int lane = pid & 31;
    int k8   = (pid >> 5) & 1;
    int n8   = (pid >> 6) & 31;
    int s    = (pid >> 11) & 1;
    int g    = (pid >> 12) & 3;
    int kc   = pid >> 14;
    int gq = lane >> 2, t4 = lane & 3;
    int n = n8 * 8 + gq;
    int kb = kc * 16 + k8 * 8 + t4;
    const float* w = s ? wR : wL;
    uint32_t v0 = to_tf32(w[((size_t)n * 256 + kb) * 4 + g]);
    uint32_t v1 = to_tf32(w[((size_t)n * 256 + kb + 4) * 4 + g]);
    uint2* dst = (uint2*)g_wt + pid;
    *dst = make_uint2(v0, v1);
}

// ---------------------------------------------------------------------------
// A pack/transpose: one thread -> 4 output fragments (16B each, coalesced).
//   a0 = x[b0+gq][m0+t4][plane], a1 = x[b0+8+gq][m0+t4][plane],
//   a2 = x[b0+gq][m0+4+t4][plane], a3 = x[b0+8+gq][m0+4+t4][plane]
// ---------------------------------------------------------------------------
__global__ void __launch_bounds__(128) sgp_xt(const float* __restrict__ x) {
    int blk = blockIdx.x;              // slab*16 + kc
    int slab = blk >> 4, kc = blk & 15;
    int t = threadIdx.x;
    float* outb = g_xt + (size_t)blk * 2048;
#pragma unroll
    for (int q = 0; q < 4; q++) {
        int f = q * 128 + t;           // fragment id 0..511
        int fb = f >> 5;               // plane*2 + k8
        int lane = f & 31;
        int plane = fb >> 1, k8 = fb & 1;
        int gq = lane >> 2, t4 = lane & 3;
        int b0 = slab * 16 + gq;
        int m0 = kc * 16 + k8 * 8 + t4;
        uint32_t v0 = to_tf32(x[(size_t)b0 * 2048 + m0 * 8 + plane]);
        uint32_t v1 = to_tf32(x[(size_t)(b0 + 8) * 2048 + m0 * 8 + plane]);
        uint32_t v2 = to_tf32(x[(size_t)b0 * 2048 + (m0 + 4) * 8 + plane]);
        uint32_t v3 = to_tf32(x[(size_t)(b0 + 8) * 2048 + (m0 + 4) * 8 + plane]);
        *(uint4*)(outb + f * 4) = make_uint4(v0, v1, v2, v3);
    }
}

// ---------------------------------------------------------------------------
// fused GEMM (tf32 mma.sync, fragment-packed smem) + norm/gp epilogue.
// CTA: 16 b x 8 planes (128 rows) x 64 n x both sides. 8 warps: wm(2) x wn(4).
// ---------------------------------------------------------------------------
__global__ void __launch_bounds__(256, 2)
sgp_gemm(const float* __restrict__ x,
         const float* __restrict__ bL,
         float* __restrict__ out) {
    extern __shared__ __align__(16) char sm[];
    float* smf = (float*)sm;

    const int tid = threadIdx.x;
    const int lane = tid & 31;
    const int wid = tid >> 5;
    const int gq = lane >> 2;
    const int t4 = lane & 3;
    const int wm = wid >> 2;           // 0..1: planes wm*4 .. wm*4+3
    const int wn = wid & 3;            // 0..3: n block of 16

    const int n0 = blockIdx.x * GBN;
    const int n8_0 = blockIdx.x * 8;
    const int slab = blockIdx.y;
    const int b0 = slab * 16;

    const uint32_t smb = smem_u32(sm);

    // cp.async plan: 10 x 16B per thread per chunk (A:2, B:8)
    uint32_t sdA[2]; const float* gsA[2];
    uint32_t sdB[8]; const float* gsB[8];
#pragma unroll
    for (int q = 0; q < 2; q++) {
        int fa = q * 256 + tid;                 // 0..511 float4 of A
        sdA[q] = smb + fa * 16;
        gsA[q] = g_xt + (size_t)slab * NCHUNK * 2048 + fa * 4;
    }
#pragma unroll
    for (int q = 0; q < 8; q++) {
        int fb = q * 256 + tid;                 // 0..2047 float4 of B
        int seg = fb >> 8;                      // g*2+s
        int r = fb & 255;
        sdB[q] = smb + A_STAGE_B + fb * 16;
        gsB[q] = g_wt + ((size_t)seg * 32 + n8_0) * 128 + r * 4;
    }

    float acc[4][2][2][4];
#pragma unroll
    for (int mt = 0; mt < 4; mt++)
#pragma unroll
        for (int nt = 0; nt < 2; nt++)
#pragma unroll
            for (int s = 0; s < 2; s++)
#pragma unroll
                for (int r = 0; r < 4; r++) acc[mt][nt][s][r] = 0.0f;

    // chunk c source offsets: A += c*2048 floats, B += c*8*32*128 floats
#pragma unroll
    for (int q = 0; q < 2; q++) cp16(sdA[q], gsA[q]);
#pragma unroll
    for (int q = 0; q < 8; q++) cp16(sdB[q], gsB[q]);
    cp_commit();

    for (int c = 0; c < NCHUNK; c++) {
        const int buf = c & 1;
        if (c < NCHUNK - 1) {
            const int nb = buf ^ 1;
            const size_t aoff = (size_t)(c + 1) * 2048;
            const size_t boff = (size_t)(c + 1) * (8 * 32 * 128);
#pragma unroll
            for (int q = 0; q < 2; q++) cp16(sdA[q] + nb * STAGE_B, gsA[q] + aoff);
#pragma unroll
            for (int q = 0; q < 8; q++) cp16(sdB[q] + nb * STAGE_B, gsB[q] + boff);
            cp_commit();
            cp_wait<1>();
        } else {
            cp_wait<0>();
        }
        __syncthreads();

        const uint32_t* As = (const uint32_t*)(sm + buf * STAGE_B);
        const uint32_t* Bs = (const uint32_t*)(sm + buf * STAGE_B + A_STAGE_B);

#pragma unroll
        for (int ks = 0; ks < 2; ks++) {
            uint32_t a[4][4];
#pragma unroll
            for (int mt = 0; mt < 4; mt++) {
                int plane = wm * 4 + mt;
                const uint4 v = *(const uint4*)(As + ((plane * 2 + ks) * 32 + lane) * 4);
                a[mt][0] = v.x; a[mt][1] = v.y; a[mt][2] = v.z; a[mt][3] = v.w;
            }
            uint32_t b[2][2][2][2];  // [gi][s][nt][h]
#pragma unroll
            for (int gi = 0; gi < 2; gi++) {
                int g = wm * 2 + gi;
#pragma unroll
                for (int s = 0; s < 2; s++)
#pragma unroll
                    for (int nt = 0; nt < 2; nt++) {
                        int n8l = wn * 2 + nt;
                        const uint2 v = *(const uint2*)(Bs +
                            ((((g * 2 + s) * 8 + n8l) * 2 + ks) * 32 + lane) * 2);
                        b[gi][s][nt][0] = v.x; b[gi][s][nt][1] = v.y;
                    }
            }
#pragma unroll
            for (int mt = 0; mt < 4; mt++) {
                int gi = (wm == 0) ? (mt > 0 ? 1 : 0) : (mt == 3 ? 1 : 0);
#pragma unroll
                for (int nt = 0; nt < 2; nt++)
#pragma unroll
                    for (int s = 0; s < 2; s++)
                        mma_tf32(acc[mt][nt][s], a[mt], b[gi][s][nt]);
            }
        }
        __syncthreads();
    }

    // ---- epilogue: exchange acc through smem, then norm/gp/bias/store ----
    // eS[(s*8+p)*16 + bl][ (nl + bl*4)&63 ]  (64KB @ smf[0])
#pragma unroll
    for (int mt = 0; mt < 4; mt++) {
        int p = wm * 4 + mt;
#pragma unroll
        for (int nt = 0; nt < 2; nt++) {
            int nlo = wn * 16 + nt * 8 + 2 * t4;
#pragma unroll
            for (int s = 0; s < 2; s++) {
                int row0 = ((s * 8 + p) * 16 + gq) * 64;
                int row1 = ((s * 8 + p) * 16 + gq + 8) * 64;
                smf[row0 + ((nlo + gq * 4) & 63)]           = acc[mt][nt][s][0];
                smf[row0 + ((nlo + 1 + gq * 4) & 63)]       = acc[mt][nt][s][1];
                smf[row1 + ((nlo + (gq + 8) * 4) & 63)]     = acc[mt][nt][s][2];
                smf[row1 + ((nlo + 1 + (gq + 8) * 4) & 63)] = acc[mt][nt][s][3];
            }
        }
    }
    __syncthreads();
    // stage Wc (64 n x 64, padded stride 65), sig, bias
#pragma unroll
    for (int q = 0; q < 16; q++) {
        int f = q * 256 + tid;              // 0..4095
        int nl = f >> 6, i = f & 63;
        smf[WC_OFF_F + nl * 65 + i] = g_Wc[(n0 + nl) * 64 + i];
    }
    {
        int f = tid;                        // 256 = 64n x 4g
        smf[SIG_OFF_F + f] = g_sig[(n0 + (f >> 2)) * 4 + (f & 3)];
        if (tid < 64) smf[BIAS_OFF_F + tid] = bL[n0 + tid];
    }
    __syncthreads();

    const int JT[64] = {
        0,1,2,3,4,5,6,7,
        1,0,4,5,2,3,7,6,
        2,4,0,6,1,7,3,5,
        3,5,6,0,7,1,2,4,
        4,2,1,7,0,6,5,3,
        5,3,7,1,6,0,4,2,
        6,7,3,2,5,4,0,1,
        7,6,5,4,3,2,1,0 };
    const float RS2 = 0.7071067811865476f;

#pragma unroll
    for (int q = 0; q < 4; q++) {
        int pid = q * 256 + tid;            // 0..1023 = bl*64 + nl
        int bl = pid >> 6, nl = pid & 63;
        int swz = (nl + bl * 4) & 63;

        float Lv[8], Rv[8];
#pragma unroll
        for (int i = 0; i < 8; i++) {
            Lv[i] = smf[((0 * 8 + i) * 16 + bl) * 64 + swz];
            Rv[i] = smf[((1 * 8 + i) * 16 + bl) * 64 + swz];
        }
        const float4* xp = (const float4*)(x + ((size_t)(b0 + bl) * FDIM + n0 + nl) * NB);
        float4 x0 = xp[0], x1 = xp[1];
        float xv[8] = {x0.x, x0.y, x0.z, x0.w, x1.x, x1.y, x1.z, x1.w};

        float qs[4];
        qs[0] = Rv[0] * Rv[0];
        qs[1] = Rv[1] * Rv[1] + Rv[2] * Rv[2] + Rv[3] * Rv[3];
        qs[2] = Rv[4] * Rv[4] + Rv[5] * Rv[5] + Rv[6] * Rv[6];
        qs[3] = Rv[7] * Rv[7];
        float inv[4];
#pragma unroll
        for (int g = 0; g < 4; g++) {
            float nm = sqrtf(sqrtf(qs[g] * qs[g] + 1e-16f));
            float sg = smf[SIG_OFF_F + nl * 4 + g];
            inv[g] = 1.0f / (sg * (nm - 1.0f) + 1.0f + 1e-6f);
        }
        float xr[8];
        xr[0] = Rv[0] * inv[0];
        xr[1] = Rv[1] * inv[1];  xr[2] = Rv[2] * inv[1];  xr[3] = Rv[3] * inv[1];
        xr[4] = Rv[4] * inv[2];  xr[5] = Rv[5] * inv[2];  xr[6] = Rv[6] * inv[2];
        xr[7] = Rv[7] * inv[3];

        const float* wc = smf + WC_OFF_F + nl * 65;
        float gp[8] = {0, 0, 0, 0, 0, 0, 0, 0};
#pragma unroll
        for (int i = 0; i < 8; i++) {
#pragma unroll
            for (int k = 0; k < 8; k++)
                gp[JT[i * 8 + k]] += wc[i * 8 + k] * xv[i] * xr[k];
        }

        float o[8];
#pragma unroll
        for (int i = 0; i < 8; i++) o[i] = (Lv[i] + gp[i]) * RS2;
        o[0] += smf[BIAS_OFF_F + nl] * RS2;

        float4* op = (float4*)(out + ((size_t)(b0 + bl) * FDIM + n0 + nl) * NB);
        op[0] = make_float4(o[0], o[1], o[2], o[3]);
        op[1] = make_float4(o[4], o[5], o[6], o[7]);
    }
}

// ---------------------------------------------------------------------------
// inputs: x, w_left, b_left, w_right, a_norm, w_gp
// ---------------------------------------------------------------------------
extern "C" void kernel_launch(void* const* d_in, const int* in_sizes, int n_in,
                              void* d_out, int out_size) {
    const float* x      = (const float*)d_in[0];
    const float* wL     = (const float*)d_in[1];
    const float* bLp    = (const float*)d_in[2];
    const float* wR     = (const float*)d_in[3];
    const float* a_norm = (const float*)d_in[4];
    const float* w_gp   = (const float*)d_in[5];
    float* out = (float*)d_out;

    sgp_prep<<<FDIM, 64>>>(w_gp, a_norm);
    sgp_wprep<<<1024, 256>>>(wL, wR);          // 262144 fragment-pairs / 256
    sgp_xt<<<NSLAB * NCHUNK, 128>>>(x);

    cudaFuncSetAttribute(sgp_gemm, cudaFuncAttributeMaxDynamicSharedMemorySize,
                         SMEM_TOTAL);
    dim3 gg(FDIM / GBN, NSLAB);        // (4, 512), n-tiles fastest for A L2 reuse
    sgp_gemm<<<gg, 256, SMEM_TOTAL>>>(x, bLp, out);
}

// round 7
// speedup vs baseline: 1.4510x; 1.4510x over previous
#include <cuda_runtime.h>
#include <cstdint>
#include <math.h>

#define FDIM 256
#define NB 8
#define NPATH 20
#define BDIM 8192
#define NROWS (NB * BDIM)          // 65536 GEMM rows (plane-major)
#define KC 32                      // k per pipeline chunk
#define NCHUNK (FDIM / KC)         // 8
#define GBN 64                     // n per CTA (per side; both sides computed)

// smem: per stage A 16KB + B 16KB; 3 stages
#define A_STAGE_B 16384
#define STAGE_B 32768
#define SMEM_TOTAL (3 * STAGE_B)   // 98304

// ---------------- scratch (device globals) ----------------
// A fragment-packed: [plane 8][btile 64][chunk 8][ks 4][m16 8][lane 32][4]
__device__ float g_xt[(size_t)NROWS * FDIM];               // 64MB
// B fragment-packed: [g 4][nt 4][chunk 8][s 2][n8l 8][ks 4][lane 32][2]
__device__ float g_wt[(size_t)4 * 4 * 8 * 4096];           // 2MB
__device__ float g_L [(size_t)FDIM * NROWS];               // 64MB [n][row]
__device__ float g_R [(size_t)FDIM * NROWS];               // 64MB [n][row]
__device__ float g_Wc[FDIM * 64];
__device__ float g_sig[FDIM * 4];

__constant__ int c_masks[8] = {0, 1, 2, 4, 3, 5, 6, 7};
__constant__ int c_plut[64] = {
     0, -1, -1, -1,   -1,  1, -1, -1,   -1, -1,  2, -1,   -1, -1, -1,  3,
    -1,  4, -1, -1,    5, -1,  6, -1,   -1,  7, -1,  8,   -1, -1,  9, -1,
    -1, -1, 10, -1,   -1, 11, -1, 12,   13, -1, 14, -1,   -1, 15, -1, -1,
    -1, -1, -1, 16,   -1, -1, 17, -1,   -1, 18, -1, -1,   19, -1, -1, -1
};
__constant__ int c_grade_of_plane[8] = {0, 1, 1, 1, 2, 2, 2, 3};

// ---------------- helpers ----------------
__device__ __forceinline__ uint32_t to_tf32(float f) {
    uint32_t r;
    asm("cvt.rna.tf32.f32 %0, %1;" : "=r"(r) : "f"(f));
    return r;
}
__device__ __forceinline__ uint32_t smem_u32(const void* p) {
    uint32_t r;
    asm("{ .reg .u64 t; cvta.to.shared.u64 t, %1; cvt.u32.u64 %0, t; }" : "=r"(r) : "l"(p));
    return r;
}
__device__ __forceinline__ void cp16(uint32_t sdst, const void* gsrc) {
    asm volatile("cp.async.cg.shared.global [%0], [%1], 16;" :: "r"(sdst), "l"(gsrc));
}
__device__ __forceinline__ void cp_commit() { asm volatile("cp.async.commit_group;"); }
template <int N> __device__ __forceinline__ void cp_wait() {
    asm volatile("cp.async.wait_group %0;" :: "n"(N));
}
__device__ __forceinline__ void mma_tf32(float* c, const uint32_t* a, const uint32_t* b) {
    asm volatile(
        "mma.sync.aligned.m16n8k8.row.col.f32.tf32.tf32.f32 "
        "{%0,%1,%2,%3}, {%4,%5,%6,%7}, {%8,%9}, {%0,%1,%2,%3};"
        : "+f"(c[0]), "+f"(c[1]), "+f"(c[2]), "+f"(c[3])
        : "r"(a[0]), "r"(a[1]), "r"(a[2]), "r"(a[3]), "r"(b[0]), "r"(b[1]));
}

// ---------------------------------------------------------------------------
// prep: Wc[n][i][k] = sign(m_i,m_k) * w_gp[n, path], sig = sigmoid(a_norm)
// ---------------------------------------------------------------------------
__global__ void sgp_prep(const float* __restrict__ w_gp,
                         const float* __restrict__ a_norm) {
    int n = blockIdx.x;
    int t = threadIdx.x;
    int i = t >> 3, k = t & 7;
    int mi = c_masks[i], mk = c_masks[k];
    int gi = __popc(mi), gj = __popc(mi ^ mk), gk = __popc(mk);
    int p = c_plut[gi * 16 + gj * 4 + gk];
    int s = 0, aa = mi >> 1;
    while (aa) { s += __popc(aa & mk); aa >>= 1; }
    float sgn = (s & 1) ? -1.0f : 1.0f;
    g_Wc[n * 64 + t] = sgn * w_gp[n * NPATH + p];
    if (t < 4) g_sig[n * 4 + t] = 1.0f / (1.0f + expf(-a_norm[n * 4 + t]));
}

// ---------------------------------------------------------------------------
// B pack: pid -> [g][nt][c][s][n8l][ks][lane] uint2 fragment slot
//   b0 = w_s[n][k+t4][g], b1 = w_s[n][k+t4+4][g]
// ---------------------------------------------------------------------------
__global__ void __launch_bounds__(256) sgp_wprep(const float* __restrict__ wL,
                                                 const float* __restrict__ wR) {
    int pid = blockIdx.x * 256 + threadIdx.x;   // 0 .. 262143
    int lane = pid & 31;
    int ks   = (pid >> 5) & 3;
    int n8l  = (pid >> 7) & 7;
    int s    = (pid >> 10) & 1;
    int c    = (pid >> 11) & 7;
    int nt   = (pid >> 14) & 3;
    int g    = (pid >> 16) & 3;
    int gq = lane >> 2, t4 = lane & 3;
    int n = nt * 64 + n8l * 8 + gq;
    int k = c * 32 + ks * 8 + t4;
    const float* w = s ? wR : wL;
    uint32_t v0 = to_tf32(w[((size_t)n * 256 + k) * 4 + g]);
    uint32_t v1 = to_tf32(w[((size_t)n * 256 + k + 4) * 4 + g]);
    ((uint2*)g_wt)[pid] = make_uint2(v0, v1);
}

// ---------------------------------------------------------------------------
// A pack/transpose: block = (btile 64, chunk 8), 256 threads = (m16 8, lane 32).
// Reads x[b][m][0..7] in full 32B sectors; writes coalesced STG.128 into
// fragment order for all 8 planes.
// ---------------------------------------------------------------------------
__global__ void __launch_bounds__(256) sgp_xt(const float* __restrict__ x) {
    int btile = blockIdx.x >> 3, chunk = blockIdx.x & 7;
    int t = threadIdx.x;
    int lane = t & 31, m16 = t >> 5;
    int gq = lane >> 2, t4 = lane & 3;
    int b0 = btile * 128 + m16 * 16 + gq;
    int k0 = chunk * 32 + t4;
#pragma unroll
    for (int ks = 0; ks < 4; ks++) {
        int kk = k0 + ks * 8;
        // four (b,m) positions, each 8 contiguous floats (all planes)
        float p00[8], p10[8], p01[8], p11[8];
        {
            const float4* q;
            q = (const float4*)(x + ((size_t)b0 * 256 + kk) * 8);
            *(float4*)&p00[0] = q[0]; *(float4*)&p00[4] = q[1];
            q = (const float4*)(x + ((size_t)(b0 + 8) * 256 + kk) * 8);
            *(float4*)&p10[0] = q[0]; *(float4*)&p10[4] = q[1];
            q = (const float4*)(x + ((size_t)b0 * 256 + kk + 4) * 8);
            *(float4*)&p01[0] = q[0]; *(float4*)&p01[4] = q[1];
            q = (const float4*)(x + ((size_t)(b0 + 8) * 256 + kk + 4) * 8);
            *(float4*)&p11[0] = q[0]; *(float4*)&p11[4] = q[1];
        }
#pragma unroll
        for (int plane = 0; plane < 8; plane++) {
            uint4 v = make_uint4(to_tf32(p00[plane]), to_tf32(p10[plane]),
                                 to_tf32(p01[plane]), to_tf32(p11[plane]));
            float* dst = g_xt + (((size_t)(plane * 64 + btile) * 8 + chunk) * 4096)
                              + ((ks * 8 + m16) * 32 + lane) * 4;
            *(uint4*)dst = v;
        }
    }
}

// ---------------------------------------------------------------------------
// tf32 mma.sync GEMM, fragment-packed smem, 3-stage cp.async pipeline.
// CTA: 128 rows (one plane) x 64 n x both sides. 8 warps: wm(2) x wn(4).
// Output col-major [n][row] into g_L / g_R.
// ---------------------------------------------------------------------------
__global__ void __launch_bounds__(256, 2)
sgp_gemm() {
    extern __shared__ __align__(16) char sm[];

    const int tid = threadIdx.x;
    const int lane = tid & 31;
    const int wid = tid >> 5;
    const int gq = lane >> 2;
    const int t4 = lane & 3;
    const int wm = wid >> 2;           // 0..1 -> m offset wm*64
    const int wn = wid & 3;            // 0..3 -> n block of 16

    const int nt = blockIdx.x;         // 0..3 (fastest: A reuse in L2)
    const int n0 = nt * GBN;
    const int rt = blockIdx.y;         // 0..511
    const int plane = rt >> 6;
    const int btile = rt & 63;
    const int grade = c_grade_of_plane[plane];

    const float* Abase = g_xt + ((size_t)(plane * 64 + btile) * 8) * 4096;
    const float* Bbase = g_wt + ((size_t)(grade * 4 + nt) * 8) * 4096;
    const uint32_t smb = smem_u32(sm);

    float acc[4][2][2][4];
#pragma unroll
    for (int mt = 0; mt < 4; mt++)
#pragma unroll
        for (int nn = 0; nn < 2; nn++)
#pragma unroll
            for (int s = 0; s < 2; s++)
#pragma unroll
                for (int r = 0; r < 4; r++) acc[mt][nn][s][r] = 0.0f;

    // issue chunk into stage buffer: A 4096 floats, B 4096 floats; 8 cp16/thread
    auto issue = [&](int c, int buf) {
        uint32_t sb = smb + buf * STAGE_B;
        const float* ga = Abase + (size_t)c * 4096;
        const float* gb = Bbase + (size_t)c * 4096;
#pragma unroll
        for (int q = 0; q < 4; q++) {
            int f = q * 256 + tid;     // float4 index 0..1023
            cp16(sb + f * 16, ga + f * 4);
            cp16(sb + A_STAGE_B + f * 16, gb + f * 4);
        }
        cp_commit();
    };

    issue(0, 0);
    issue(1, 1);

    for (int c = 0; c < NCHUNK; c++) {
        const int buf = c % 3;
        if (c < NCHUNK - 1) cp_wait<1>(); else cp_wait<0>();
        __syncthreads();

        const uint32_t* As = (const uint32_t*)(sm + buf * STAGE_B);
        const uint32_t* Bs = (const uint32_t*)(sm + buf * STAGE_B + A_STAGE_B);

#pragma unroll
        for (int ks = 0; ks < 4; ks++) {
            uint32_t a[4][4];
#pragma unroll
            for (int mt = 0; mt < 4; mt++) {
                const uint4 v = *(const uint4*)(As + ((ks * 8 + wm * 4 + mt) * 32 + lane) * 4);
                a[mt][0] = v.x; a[mt][1] = v.y; a[mt][2] = v.z; a[mt][3] = v.w;
            }
            uint32_t b[2][2][2];   // [s][nn][h]
#pragma unroll
            for (int s = 0; s < 2; s++)
#pragma unroll
                for (int nn = 0; nn < 2; nn++) {
                    const uint2 v = *(const uint2*)(Bs +
                        ((s * 8 + wn * 2 + nn) * 4 + ks) * 64 + lane * 2);
                    b[s][nn][0] = v.x; b[s][nn][1] = v.y;
                }
#pragma unroll
            for (int mt = 0; mt < 4; mt++)
#pragma unroll
                for (int nn = 0; nn < 2; nn++)
#pragma unroll
                    for (int s = 0; s < 2; s++)
                        mma_tf32(acc[mt][nn][s], a[mt], b[s][nn]);
        }
        if (c + 2 < NCHUNK) issue(c + 2, (c + 2) % 3);
    }

    // store: col-major [n][row]; 32B sectors fully covered per warp
    const int rbase = plane * 8192 + btile * 128;
#pragma unroll
    for (int s = 0; s < 2; s++) {
        float* Ob = s ? g_R : g_L;
#pragma unroll
        for (int mt = 0; mt < 4; mt++) {
#pragma unroll
            for (int nn = 0; nn < 2; nn++) {
                int row = rbase + wm * 64 + mt * 16 + gq;
                int col = n0 + wn * 16 + nn * 8 + 2 * t4;
                Ob[(size_t)col * NROWS + row]           = acc[mt][nn][s][0];
                Ob[(size_t)(col + 1) * NROWS + row]     = acc[mt][nn][s][1];
                Ob[(size_t)col * NROWS + row + 8]       = acc[mt][nn][s][2];
                Ob[(size_t)(col + 1) * NROWS + row + 8] = acc[mt][nn][s][3];
            }
        }
    }
}

// ---------------------------------------------------------------------------
// epilogue: norm(R) -> xr, gp = x ⊗_Wc xr, out = (L + gp + bias)/sqrt(2)
// one warp = 32 consecutive b at a fixed n (validated in R3)
// ---------------------------------------------------------------------------
__global__ void __launch_bounds__(256) sgp_epi(const float* __restrict__ x,
                                               const float* __restrict__ bL,
                                               float* __restrict__ out) {
    int wg = blockIdx.x * 8 + (threadIdx.x >> 5);
    int lane = threadIdx.x & 31;
    int n = wg & 255;
    int b = ((wg >> 8) << 5) + lane;

    float Lv[8], Rv[8];
#pragma unroll
    for (int i = 0; i < 8; i++) {
        size_t row = (size_t)i * BDIM + b;
        Lv[i] = g_L[(size_t)n * NROWS + row];
        Rv[i] = g_R[(size_t)n * NROWS + row];
    }
    const float4* xp = (const float4*)(x + ((size_t)b * FDIM + n) * NB);
    float4 x0 = xp[0], x1 = xp[1];
    float xv[8] = {x0.x, x0.y, x0.z, x0.w, x1.x, x1.y, x1.z, x1.w};

    float qs[4];
    qs[0] = Rv[0] * Rv[0];
    qs[1] = Rv[1] * Rv[1] + Rv[2] * Rv[2] + Rv[3] * Rv[3];
    qs[2] = Rv[4] * Rv[4] + Rv[5] * Rv[5] + Rv[6] * Rv[6];
    qs[3] = Rv[7] * Rv[7];
    float inv[4];
#pragma unroll
    for (int g = 0; g < 4; g++) {
        float nm = sqrtf(sqrtf(qs[g] * qs[g] + 1e-16f));
        float sg = g_sig[n * 4 + g];
        inv[g] = 1.0f / (sg * (nm - 1.0f) + 1.0f + 1e-6f);
    }
    float xr[8];
    xr[0] = Rv[0] * inv[0];
    xr[1] = Rv[1] * inv[1];  xr[2] = Rv[2] * inv[1];  xr[3] = Rv[3] * inv[1];
    xr[4] = Rv[4] * inv[2];  xr[5] = Rv[5] * inv[2];  xr[6] = Rv[6] * inv[2];
    xr[7] = Rv[7] * inv[3];

    const int JT[64] = {
        0,1,2,3,4,5,6,7,
        1,0,4,5,2,3,7,6,
        2,4,0,6,1,7,3,5,
        3,5,6,0,7,1,2,4,
        4,2,1,7,0,6,5,3,
        5,3,7,1,6,0,4,2,
        6,7,3,2,5,4,0,1,
        7,6,5,4,3,2,1,0 };
    const float* wc = g_Wc + n * 64;
    float gp[8] = {0, 0, 0, 0, 0, 0, 0, 0};
#pragma unroll
    for (int i = 0; i < 8; i++) {
#pragma unroll
        for (int k = 0; k < 8; k++)
            gp[JT[i * 8 + k]] += wc[i * 8 + k] * xv[i] * xr[k];
    }

    const float RS2 = 0.7071067811865476f;
    float o[8];
#pragma unroll
    for (int i = 0; i < 8; i++) o[i] = (Lv[i] + gp[i]) * RS2;
    o[0] += bL[n] * RS2;

    float4* op = (float4*)(out + ((size_t)b * FDIM + n) * NB);
    op[0] = make_float4(o[0], o[1], o[2], o[3]);
    op[1] = make_float4(o[4], o[5], o[6], o[7]);
}

// ---------------------------------------------------------------------------
// inputs: x, w_left, b_left, w_right, a_norm, w_gp
// ---------------------------------------------------------------------------
extern "C" void kernel_launch(void* const* d_in, const int* in_sizes, int n_in,
                              void* d_out, int out_size) {
    const float* x      = (const float*)d_in[0];
    const float* wL     = (const float*)d_in[1];
    const float* bLp    = (const float*)d_in[2];
    const float* wR     = (const float*)d_in[3];
    const float* a_norm = (const float*)d_in[4];
    const float* w_gp   = (const float*)d_in[5];
    float* out = (float*)d_out;

    sgp_prep<<<FDIM, 64>>>(w_gp, a_norm);
    sgp_wprep<<<1024, 256>>>(wL, wR);      // 262144 fragment-pairs
    sgp_xt<<<512, 256>>>(x);               // (btile 64) x (chunk 8)

    cudaFuncSetAttribute(sgp_gemm, cudaFuncAttributeMaxDynamicSharedMemorySize,
                         SMEM_TOTAL);
    dim3 gg(4, 512);                       // n-tiles fastest for A L2 reuse
    sgp_gemm<<<gg, 256, SMEM_TOTAL>>>();

    sgp_epi<<<(BDIM * FDIM) / 256, 256>>>(x, bLp, out);
}